// round 2
// baseline (speedup 1.0000x reference)
#include <cuda_runtime.h>
#include <cstdint>

#define SEQ 2048
#define DK  128

// ---------------- static device scratch (no allocations allowed) ------------
__device__ float  g_Pqk[(size_t)SEQ * SEQ];   // P_qk[i][l] = q_i . k_l
__device__ float  g_Pvv[(size_t)SEQ * SEQ];   // P_vv[i][l] = v_i . v_l
__device__ float  g_U[(size_t)SEQ * DK];      // u_l = Sqq_l k_l
__device__ float4 g_scal[SEQ];                // {s_l, k^T Sqq k, v.v, 0}

// ---------------- f32x2 packed helpers (sm_103a) ----------------------------
__device__ __forceinline__ unsigned long long ffma2(unsigned long long a,
                                                    unsigned long long b,
                                                    unsigned long long c) {
    unsigned long long d;
    asm("fma.rn.f32x2 %0, %1, %2, %3;" : "=l"(d) : "l"(a), "l"(b), "l"(c));
    return d;
}
__device__ __forceinline__ unsigned long long fmul2(unsigned long long a,
                                                    unsigned long long b) {
    unsigned long long d;
    asm("mul.rn.f32x2 %0, %1, %2;" : "=l"(d) : "l"(a), "l"(b));
    return d;
}
__device__ __forceinline__ unsigned long long pk2(float lo, float hi) {
    unsigned long long r;
    asm("mov.b64 %0, {%1, %2};" : "=l"(r) : "f"(lo), "f"(hi));
    return r;
}
__device__ __forceinline__ float2 upk2(unsigned long long a) {
    float2 f;
    asm("mov.b64 {%0, %1}, %2;" : "=f"(f.x), "=f"(f.y) : "l"(a));
    return f;
}

// ---------------- Phase 1a: both Gram matrices in one launch ----------------
// z==0: Pqk[i][l] = q_i.k_l ; z==1: Pvv[i][l] = v_i.v_l.
// Only i-block <= l-block needed (consumers mask i<=l).
__global__ void __launch_bounds__(256) k_gemm(const float* __restrict__ q,
                                              const float* __restrict__ kk_,
                                              const float* __restrict__ v) {
    if (blockIdx.y > blockIdx.x) return;
    const float* A; const float* B; float* C;
    if (blockIdx.z == 0) { A = q; B = kk_; C = g_Pqk; }
    else                 { A = v; B = v;   C = g_Pvv; }
    __shared__ float As[32][68];   // k-major: As[kk][row]
    __shared__ float Bs[32][68];
    const int tx = threadIdx.x & 15, ty = threadIdx.x >> 4;
    const int i0 = blockIdx.y * 64, l0 = blockIdx.x * 64;
    const int t = threadIdx.x;
    const int r = t >> 2, cc = (t & 3) * 8;
    float acc[4][4] = {};
    for (int k0 = 0; k0 < DK; k0 += 32) {
        float4 a0 = *(const float4*)&A[(size_t)(i0 + r) * DK + k0 + cc];
        float4 a1 = *(const float4*)&A[(size_t)(i0 + r) * DK + k0 + cc + 4];
        float4 b0 = *(const float4*)&B[(size_t)(l0 + r) * DK + k0 + cc];
        float4 b1 = *(const float4*)&B[(size_t)(l0 + r) * DK + k0 + cc + 4];
        __syncthreads();
        As[cc + 0][r] = a0.x; As[cc + 1][r] = a0.y; As[cc + 2][r] = a0.z; As[cc + 3][r] = a0.w;
        As[cc + 4][r] = a1.x; As[cc + 5][r] = a1.y; As[cc + 6][r] = a1.z; As[cc + 7][r] = a1.w;
        Bs[cc + 0][r] = b0.x; Bs[cc + 1][r] = b0.y; Bs[cc + 2][r] = b0.z; Bs[cc + 3][r] = b0.w;
        Bs[cc + 4][r] = b1.x; Bs[cc + 5][r] = b1.y; Bs[cc + 6][r] = b1.z; Bs[cc + 7][r] = b1.w;
        __syncthreads();
#pragma unroll
        for (int kv = 0; kv < 32; kv++) {
            float4 av = *(const float4*)&As[kv][ty * 4];
            float4 bv = *(const float4*)&Bs[kv][tx * 4];
            float a[4] = {av.x, av.y, av.z, av.w};
            float b[4] = {bv.x, bv.y, bv.z, bv.w};
#pragma unroll
            for (int i = 0; i < 4; i++)
#pragma unroll
                for (int j = 0; j < 4; j++) acc[i][j] += a[i] * b[j];
        }
    }
#pragma unroll
    for (int i = 0; i < 4; i++) {
        float4 o = make_float4(acc[i][0], acc[i][1], acc[i][2], acc[i][3]);
        *(float4*)&C[(size_t)(i0 + ty * 4 + i) * SEQ + l0 + tx * 4] = o;
    }
}

// ---------------- Phase 1b: U[l][d] = (1/l) sum_{i<=l} Pqk[i][l] * Q[i][d] --
__global__ void __launch_bounds__(256) k_U(const float* __restrict__ Q) {
    __shared__ float sh[128][8];
    const int tid = threadIdx.x;
    const int d = tid & 127, jh = tid >> 7;
    const int l0 = blockIdx.x * 8;
    float acc[4] = {0.f, 0.f, 0.f, 0.f};
    for (int i0 = 0; i0 <= l0 + 7; i0 += 128) {
        const int r = tid >> 1, c4 = (tid & 1) * 4;
        const int irow = i0 + r;
        float4 pv = *(const float4*)&g_Pqk[(size_t)irow * SEQ + l0 + c4];
        if (irow > l0 + c4 + 0) pv.x = 0.f;
        if (irow > l0 + c4 + 1) pv.y = 0.f;
        if (irow > l0 + c4 + 2) pv.z = 0.f;
        if (irow > l0 + c4 + 3) pv.w = 0.f;
        __syncthreads();
        *(float4*)&sh[r][c4] = pv;
        __syncthreads();
#pragma unroll 8
        for (int r2 = 0; r2 < 128; r2++) {
            float qv = Q[(size_t)(i0 + r2) * DK + d];
            float4 s4 = *(const float4*)&sh[r2][jh * 4];
            acc[0] += qv * s4.x; acc[1] += qv * s4.y;
            acc[2] += qv * s4.z; acc[3] += qv * s4.w;
        }
    }
#pragma unroll
    for (int jl = 0; jl < 4; jl++) {
        const int l = l0 + jh * 4 + jl;
        g_U[(size_t)l * DK + d] = acc[jl] / (float)(l + 1);
    }
}

// ---------------- Phase 1c: per-step scalars (coalesced) --------------------
// Block handles 64 columns; row-major tiled reads with causal predication.
__global__ void __launch_bounds__(256) k_scal() {
    const int tid = threadIdx.x;
    const int c = tid & 63;       // column within block
    const int rq = tid >> 6;      // 0..3 row quarter
    const int l0 = blockIdx.x * 64;
    const int l = l0 + c;
    float ss = 0.f, k2 = 0.f;
    const int ntiles = blockIdx.x + 1;
    for (int tt = 0; tt < ntiles; tt++) {
        const int ib = tt * 64 + rq * 16;
#pragma unroll 4
        for (int j = 0; j < 16; j++) {
            const int i = ib + j;
            if (i <= l) {
                float pq = g_Pqk[(size_t)i * SEQ + l];
                float pv = g_Pvv[(size_t)i * SEQ + l];
                ss += pq * pv;
                k2 += pq * pq;
            }
        }
    }
    __shared__ float rs[4][64], rk[4][64];
    rs[rq][c] = ss; rk[rq][c] = k2;
    __syncthreads();
    if (tid < 64) {
        float s  = rs[0][tid] + rs[1][tid] + rs[2][tid] + rs[3][tid];
        float kq = rk[0][tid] + rk[1][tid] + rk[2][tid] + rk[3][tid];
        const int ll = l0 + tid;
        const float fl = (float)(ll + 1);
        const float vv = g_Pvv[(size_t)ll * SEQ + ll];
        g_scal[ll] = make_float4(s / fl, kq / fl, vv, 0.f);
    }
}

// ---------------- Phase 2: sequential J recursion (single block) ------------
// 512 threads: seg = tid>>7 (column-segment), row = tid&127.
// J is kept UNNORMALIZED: true J = sigma * Jhat. Update becomes a single
// ffma2 per 2 elements; sigma tracked redundantly by every thread.
__global__ void __launch_bounds__(512) k_seq(const float* __restrict__ q,
                                             const float* __restrict__ kg,
                                             const float* __restrict__ v,
                                             float* __restrict__ out) {
    __shared__ float  qsh[2][128], ksh[2][128], vsh[2][128], ush[2][128];
    __shared__ float2 part[512];
    __shared__ float4 wsum[4];

    const int tid = threadIdx.x;
    const int seg = tid >> 7;
    const int row = tid & 127;
    const int lane = tid & 127;
    const float* src = (seg == 0) ? q : (seg == 1) ? kg : (seg == 2) ? v : g_U;

    unsigned long long Jp[16];
#pragma unroll
    for (int c = 0; c < 16; c++) Jp[c] = 0ull;
    float S = 0.f, T = 0.f, trS = 0.f, sigma = 1.f;

    // prologue: stage step 0, prefetch step 1 + scalars
    if (seg == 0)      qsh[0][lane] = q[lane];
    else if (seg == 1) ksh[0][lane] = kg[lane];
    else if (seg == 2) vsh[0][lane] = v[lane];
    else               ush[0][lane] = g_U[lane];
    float nx = src[(size_t)1 * DK + lane];
    float4 sc_cur  = g_scal[0];
    float4 sc_next = g_scal[1];
    __syncthreads();

    for (int l = 0; l < SEQ; l++) {
        const int b = l & 1, nb = 1 - b;

        // fire depth-2 prefetches (step l+2) — latency spans a full iteration
        float nx2 = 0.f;
        float4 nsc2 = make_float4(0.f, 0.f, 0.f, 0.f);
        if (l + 2 < SEQ) {
            nx2  = src[(size_t)(l + 2) * DK + lane];
            nsc2 = g_scal[l + 2];
        }
        // stage step l+1 into the other buffer (covered by bar1)
        if (l + 1 < SEQ) {
            if (seg == 0)      qsh[nb][lane] = nx;
            else if (seg == 1) ksh[nb][lane] = nx;
            else if (seg == 2) vsh[nb][lane] = nx;
            else               ush[nb][lane] = nx;
        }
        // pull k-segment and v[row] into registers (phase D is smem-free)
        unsigned long long kreg[16];
        {
            const ulonglong2* kp = (const ulonglong2*)&ksh[b][seg * 32];
#pragma unroll
            for (int c2 = 0; c2 < 8; c2++) {
                ulonglong2 kv = kp[c2];
                kreg[2 * c2] = kv.x; kreg[2 * c2 + 1] = kv.y;
            }
        }
        const float vreg = vsh[b][row];

        // --- phase A: packed matvec partials p1=(Jhat q)|seg, p2=(Jhat u)|seg
        float p1, p2;
        {
            unsigned long long a1a = 0ull, a1b = 0ull, a2a = 0ull, a2b = 0ull;
            const ulonglong2* qp = (const ulonglong2*)&qsh[b][seg * 32];
            const ulonglong2* up = (const ulonglong2*)&ush[b][seg * 32];
#pragma unroll
            for (int c2 = 0; c2 < 4; c2++) {
                ulonglong2 q0 = qp[2 * c2], q1 = qp[2 * c2 + 1];
                ulonglong2 u0 = up[2 * c2], u1 = up[2 * c2 + 1];
                a1a = ffma2(Jp[4 * c2 + 0], q0.x, a1a);
                a1b = ffma2(Jp[4 * c2 + 1], q0.y, a1b);
                a1a = ffma2(Jp[4 * c2 + 2], q1.x, a1a);
                a1b = ffma2(Jp[4 * c2 + 3], q1.y, a1b);
                a2a = ffma2(Jp[4 * c2 + 0], u0.x, a2a);
                a2b = ffma2(Jp[4 * c2 + 1], u0.y, a2b);
                a2a = ffma2(Jp[4 * c2 + 2], u1.x, a2a);
                a2b = ffma2(Jp[4 * c2 + 3], u1.y, a2b);
            }
            float2 f1a = upk2(a1a), f1b = upk2(a1b);
            float2 f2a = upk2(a2a), f2b = upk2(a2b);
            p1 = (f1a.x + f1a.y) + (f1b.x + f1b.y);
            p2 = (f2a.x + f2a.y) + (f2b.x + f2b.y);
        }
        part[tid] = make_float2(p1, p2);
        __syncthreads();   // bar1

        // --- reduce: combine partials, apply sigma, 3-scalar shfl tree ------
        if (tid < 128) {
            float asum = part[tid].x + part[tid + 128].x + part[tid + 256].x + part[tid + 384].x;
            float bsum = part[tid].y + part[tid + 128].y + part[tid + 256].y + part[tid + 384].y;
            float a  = sigma * asum;
            float bb = sigma * bsum;
            float x1 = vreg * a;    // v . (Jq)
            float x2 = a * a;       // ||Jq||^2
            float x3 = vreg * bb;   // v . (Ju)
#pragma unroll
            for (int o = 16; o > 0; o >>= 1) {
                x1 += __shfl_down_sync(0xffffffffu, x1, o);
                x2 += __shfl_down_sync(0xffffffffu, x2, o);
                x3 += __shfl_down_sync(0xffffffffu, x3, o);
            }
            if ((tid & 31) == 0) wsum[tid >> 5] = make_float4(x1, x2, x3, 0.f);
        }
        __syncthreads();   // bar2

        // --- phase D: scalar chain (redundant on all threads, fast rcp) -----
        float4 w0 = wsum[0], w1 = wsum[1], w2 = wsum[2], w3 = wsum[3];
        const float vJq = w0.x + w1.x + w2.x + w3.x;
        const float aa  = w0.y + w1.y + w2.y + w3.y;
        const float vJu = w0.z + w1.z + w2.z + w3.z;

        const float fl = (float)(l + 1);
        const float bm = __fdividef(1.0f, fl);
        const float am = (fl - 1.0f) * bm;

        trS = am * trS + sc_cur.z * bm;
        const float sJ   = am * S + bm * vJq;
        const float A_JJ = am * T + bm * aa;
        const float A_Jl = vJu;
        const float A_ll = sc_cur.z * sc_cur.y;
        const float s_l  = sc_cur.x;

        const bool first = (l == 0);
        const float A_JJ_s = (first || A_JJ == 0.f) ? 1.f : A_JJ;
        const float A_ll_s = (first || A_ll == 0.f) ? 1.f : A_ll;
        const float denom  = A_JJ * A_ll - A_Jl * A_Jl;
        const float denom_s = (first || denom == 0.f) ? 1.f : denom;

        const float margin = s_l - A_Jl * __fdividef(sJ, A_JJ_s);
        const float rden = __fdividef(1.0f, denom_s);
        const float wf = (A_ll * sJ - A_Jl * s_l) * rden;
        const float wi = (A_JJ * s_l - A_Jl * sJ) * rden;
        const float wf_c = (wi <= 0.f) ? __fdividef(sJ, A_JJ_s) : ((wf <= 0.f) ? 0.f : wf);
        const float wi_c = (wi <= 0.f) ? 0.f : ((wf <= 0.f) ? __fdividef(s_l, A_ll_s) : wi);
        const bool do_upd = margin > 0.f;

        float cf, ci, upd;
        if (first) {
            cf = 0.f; ci = 1.f; upd = 1.f;
            S = s_l; T = A_ll;
        } else if (do_upd) {
            cf = wf_c; ci = wi_c; upd = 1.f;
            S = cf * sJ + ci * s_l;
            T = cf * cf * A_JJ + 2.f * cf * ci * A_Jl + ci * ci * A_ll;
        } else {
            cf = 1.f; ci = 0.f; upd = 0.f;
            S = sJ; T = A_JJ;
        }
        if (tid == 0) {
            out[l] = 0.5f * trS - S + 0.5f * T;
            out[SEQ + l] = upd;
        }

        // --- Jhat update: single ffma2 per 2 elements (sigma absorbs cf) ----
        if (first || do_upd) {
            if (cf == 0.f) {
                const float civ = ci * vreg;
                const unsigned long long civp = pk2(civ, civ);
#pragma unroll
                for (int c = 0; c < 16; c++) Jp[c] = fmul2(civp, kreg[c]);
                sigma = 1.f;
            } else {
                const float rv = ci * __fdividef(1.0f, cf * sigma) * vreg;
                const unsigned long long rvp = pk2(rv, rv);
#pragma unroll
                for (int c = 0; c < 16; c++) Jp[c] = ffma2(rvp, kreg[c], Jp[c]);
                sigma *= cf;
            }
            if (sigma < 1e-16f || sigma > 1e16f) {
                const unsigned long long sp = pk2(sigma, sigma);
#pragma unroll
                for (int c = 0; c < 16; c++) Jp[c] = fmul2(sp, Jp[c]);
                sigma = 1.f;
            }
        }

        // rotate prefetch registers
        nx = nx2; sc_cur = sc_next; sc_next = nsc2;
    }

    // final J = sigma * Jhat
#pragma unroll
    for (int c = 0; c < 16; c++) {
        float2 jf = upk2(Jp[c]);
        out[2 * SEQ + (size_t)row * DK + seg * 32 + 2 * c + 0] = sigma * jf.x;
        out[2 * SEQ + (size_t)row * DK + seg * 32 + 2 * c + 1] = sigma * jf.y;
    }
}

// ---------------------------------------------------------------------------
extern "C" void kernel_launch(void* const* d_in, const int* in_sizes, int n_in,
                              void* d_out, int out_size) {
    const float* q = (const float*)d_in[0];
    const float* k = (const float*)d_in[1];
    const float* v = (const float*)d_in[2];
    float* out = (float*)d_out;

    dim3 gg(SEQ / 64, SEQ / 64, 2);
    k_gemm<<<gg, 256>>>(q, k, v);     // P_qk and P_vv in one launch
    k_U<<<SEQ / 8, 256>>>(q);
    k_scal<<<SEQ / 64, 256>>>();
    k_seq<<<1, 512>>>(q, k, v, out);
    (void)in_sizes; (void)n_in; (void)out_size;
}

// round 3
// speedup vs baseline: 1.1425x; 1.1425x over previous
#include <cuda_runtime.h>
#include <cstdint>

#define SEQ 2048
#define DK  128

// ---------------- static device scratch (no allocations allowed) ------------
__device__ float g_Pqk[(size_t)SEQ * SEQ];   // P_qk[i][l] = q_i . k_l
__device__ float g_Pvv[(size_t)SEQ * SEQ];   // P_vv[i][l] = v_i . v_l
__device__ float g_U[(size_t)SEQ * DK];      // u_l = Sqq_l k_l (includes 1/(l+1))
// per-step chain constants: [l*8+0..3] = {s_l, kqq_l, vv_l, 0}
//                           [l*8+4..7] = {kq_l, ku_l, vvm_l, 0}
__device__ float g_chain[(size_t)SEQ * 8];

// ---------------- f32x2 packed helpers (sm_103a) ----------------------------
__device__ __forceinline__ unsigned long long ffma2(unsigned long long a,
                                                    unsigned long long b,
                                                    unsigned long long c) {
    unsigned long long d;
    asm("fma.rn.f32x2 %0, %1, %2, %3;" : "=l"(d) : "l"(a), "l"(b), "l"(c));
    return d;
}
__device__ __forceinline__ unsigned long long fmul2(unsigned long long a,
                                                    unsigned long long b) {
    unsigned long long d;
    asm("mul.rn.f32x2 %0, %1, %2;" : "=l"(d) : "l"(a), "l"(b));
    return d;
}
__device__ __forceinline__ unsigned long long pk2(float lo, float hi) {
    unsigned long long r;
    asm("mov.b64 %0, {%1, %2};" : "=l"(r) : "f"(lo), "f"(hi));
    return r;
}
__device__ __forceinline__ float2 upk2(unsigned long long a) {
    float2 f;
    asm("mov.b64 {%0, %1}, %2;" : "=f"(f.x), "=f"(f.y) : "l"(a));
    return f;
}

// ---------------- Phase 1a: both Gram matrices in one launch ----------------
__global__ void __launch_bounds__(256) k_gemm(const float* __restrict__ q,
                                              const float* __restrict__ kk_,
                                              const float* __restrict__ v) {
    if (blockIdx.y > blockIdx.x) return;   // only upper blocks needed
    const float* A; const float* B; float* C;
    if (blockIdx.z == 0) { A = q; B = kk_; C = g_Pqk; }
    else                 { A = v; B = v;   C = g_Pvv; }
    __shared__ float As[32][68];   // k-major
    __shared__ float Bs[32][68];
    const int tx = threadIdx.x & 15, ty = threadIdx.x >> 4;
    const int i0 = blockIdx.y * 64, l0 = blockIdx.x * 64;
    const int t = threadIdx.x;
    const int r = t >> 2, cc = (t & 3) * 8;
    float acc[4][4] = {};
    for (int k0 = 0; k0 < DK; k0 += 32) {
        float4 a0 = *(const float4*)&A[(size_t)(i0 + r) * DK + k0 + cc];
        float4 a1 = *(const float4*)&A[(size_t)(i0 + r) * DK + k0 + cc + 4];
        float4 b0 = *(const float4*)&B[(size_t)(l0 + r) * DK + k0 + cc];
        float4 b1 = *(const float4*)&B[(size_t)(l0 + r) * DK + k0 + cc + 4];
        __syncthreads();
        As[cc + 0][r] = a0.x; As[cc + 1][r] = a0.y; As[cc + 2][r] = a0.z; As[cc + 3][r] = a0.w;
        As[cc + 4][r] = a1.x; As[cc + 5][r] = a1.y; As[cc + 6][r] = a1.z; As[cc + 7][r] = a1.w;
        Bs[cc + 0][r] = b0.x; Bs[cc + 1][r] = b0.y; Bs[cc + 2][r] = b0.z; Bs[cc + 3][r] = b0.w;
        Bs[cc + 4][r] = b1.x; Bs[cc + 5][r] = b1.y; Bs[cc + 6][r] = b1.z; Bs[cc + 7][r] = b1.w;
        __syncthreads();
#pragma unroll
        for (int kv = 0; kv < 32; kv++) {
            float4 av = *(const float4*)&As[kv][ty * 4];
            float4 bv = *(const float4*)&Bs[kv][tx * 4];
            float a[4] = {av.x, av.y, av.z, av.w};
            float b[4] = {bv.x, bv.y, bv.z, bv.w};
#pragma unroll
            for (int i = 0; i < 4; i++)
#pragma unroll
                for (int j = 0; j < 4; j++) acc[i][j] += a[i] * b[j];
        }
    }
#pragma unroll
    for (int i = 0; i < 4; i++) {
        float4 o = make_float4(acc[i][0], acc[i][1], acc[i][2], acc[i][3]);
        *(float4*)&C[(size_t)(i0 + ty * 4 + i) * SEQ + l0 + tx * 4] = o;
    }
}

// ---------------- Phase 1b: U[l][d] = (1/(l+1)) sum_{i<=l} Pqk[i][l] Q[i][d]
__global__ void __launch_bounds__(256) k_U(const float* __restrict__ Q) {
    __shared__ float sh[128][8];
    const int tid = threadIdx.x;
    const int d = tid & 127, jh = tid >> 7;
    const int l0 = blockIdx.x * 8;
    float acc[4] = {0.f, 0.f, 0.f, 0.f};
    for (int i0 = 0; i0 <= l0 + 7; i0 += 128) {
        const int r = tid >> 1, c4 = (tid & 1) * 4;
        const int irow = i0 + r;
        float4 pv = *(const float4*)&g_Pqk[(size_t)irow * SEQ + l0 + c4];
        if (irow > l0 + c4 + 0) pv.x = 0.f;
        if (irow > l0 + c4 + 1) pv.y = 0.f;
        if (irow > l0 + c4 + 2) pv.z = 0.f;
        if (irow > l0 + c4 + 3) pv.w = 0.f;
        __syncthreads();
        *(float4*)&sh[r][c4] = pv;
        __syncthreads();
#pragma unroll 8
        for (int r2 = 0; r2 < 128; r2++) {
            float qv = Q[(size_t)(i0 + r2) * DK + d];
            float4 s4 = *(const float4*)&sh[r2][jh * 4];
            acc[0] += qv * s4.x; acc[1] += qv * s4.y;
            acc[2] += qv * s4.z; acc[3] += qv * s4.w;
        }
    }
#pragma unroll
    for (int jl = 0; jl < 4; jl++) {
        const int l = l0 + jh * 4 + jl;
        g_U[(size_t)l * DK + d] = acc[jl] / (float)(l + 1);
    }
}

// ---------------- Phase 1c: per-step scalars ------------------------------
__global__ void __launch_bounds__(256) k_scal() {
    const int tid = threadIdx.x;
    const int c = tid & 63;
    const int rq = tid >> 6;
    const int l0 = blockIdx.x * 64;
    const int l = l0 + c;
    float ss = 0.f, k2 = 0.f;
    const int ntiles = blockIdx.x + 1;
    for (int tt = 0; tt < ntiles; tt++) {
        const int ib = tt * 64 + rq * 16;
#pragma unroll 4
        for (int j = 0; j < 16; j++) {
            const int i = ib + j;
            if (i <= l) {
                float pq = g_Pqk[(size_t)i * SEQ + l];
                float pv = g_Pvv[(size_t)i * SEQ + l];
                ss += pq * pv;
                k2 += pq * pq;
            }
        }
    }
    __shared__ float rs[4][64], rk[4][64];
    rs[rq][c] = ss; rk[rq][c] = k2;
    __syncthreads();
    if (tid < 64) {
        float s  = rs[0][tid] + rs[1][tid] + rs[2][tid] + rs[3][tid];
        float kq = rk[0][tid] + rk[1][tid] + rk[2][tid] + rk[3][tid];
        const int ll = l0 + tid;
        const float fl = (float)(ll + 1);
        const float vv = g_Pvv[(size_t)ll * SEQ + ll];
        *(float4*)&g_chain[(size_t)ll * 8] = make_float4(s / fl, kq / fl, vv, 0.f);
    }
}

// ---------------- Phase 1d: adjacency dots {kq, ku, vvm} --------------------
// kq_l = k_{l-1}.q_l ; ku_l = k_{l-1}.u_l ; vvm_l = v_{l-1}.v_l
__global__ void __launch_bounds__(128) k_adj(const float* __restrict__ q,
                                             const float* __restrict__ kk_,
                                             const float* __restrict__ v) {
    const int l = blockIdx.x, t = threadIdx.x;
    float kq = 0.f, ku = 0.f, vvm = 0.f;
    if (l > 0) {
        float kkv = kk_[(size_t)(l - 1) * DK + t];
        kq  = kkv * q[(size_t)l * DK + t];
        ku  = kkv * g_U[(size_t)l * DK + t];
        vvm = v[(size_t)(l - 1) * DK + t] * v[(size_t)l * DK + t];
    }
#pragma unroll
    for (int o = 16; o > 0; o >>= 1) {
        kq  += __shfl_down_sync(0xffffffffu, kq, o);
        ku  += __shfl_down_sync(0xffffffffu, ku, o);
        vvm += __shfl_down_sync(0xffffffffu, vvm, o);
    }
    __shared__ float r[3][4];
    if ((t & 31) == 0) { r[0][t >> 5] = kq; r[1][t >> 5] = ku; r[2][t >> 5] = vvm; }
    __syncthreads();
    if (t == 0) {
        float a = r[0][0] + r[0][1] + r[0][2] + r[0][3];
        float b = r[1][0] + r[1][1] + r[1][2] + r[1][3];
        float cM = r[2][0] + r[2][1] + r[2][2] + r[2][3];
        *(float4*)&g_chain[(size_t)l * 8 + 4] = make_float4(a, b, cM, 0.f);
    }
}

// ---------------- Phase 2: pipelined sequential recursion -------------------
// 512 threads, seg=tid>>7, row=tid&127; J[row][seg*32..+32) in 16 x f32x2 regs.
// Lag-2 pipeline: iteration i computes raw reductions B(i) vs Jhat_{i-2};
// warp 0 concurrently runs the scalar chain for step i-1 and publishes the
// rank-1 update coefficients (m, beta) applied by all warps at iteration i+1.
__global__ void __launch_bounds__(512) k_seq(const float* __restrict__ q,
                                             const float* __restrict__ kg,
                                             const float* __restrict__ v,
                                             float* __restrict__ out) {
    __shared__ float  qsh[2][128], ush[2][128];
    __shared__ float  ksh[4][128], vsh[4][128];
    __shared__ float2 part[512];
    __shared__ float4 wsumb[2][4];
    __shared__ float4 coeff[2];
    __shared__ float  sigf;

    const int tid = threadIdx.x;
    const int seg = tid >> 7;
    const int row = tid & 127;
    const int lane = tid & 127;

    unsigned long long Jp[16];
#pragma unroll
    for (int c = 0; c < 16; c++) Jp[c] = 0ull;

    // warp0 chain state
    float S = 0.f, T = 0.f, trS = 0.f;
    float sig_m = 1.f, sig_p = 1.f;     // sigma_{l-2}, sigma_{l-1}
    float cp = 0.f, dp = 0.f;           // coeffs of step l-1
    float vvprev = 0.f;
    float4 pA = make_float4(0, 0, 0, 0), pB = make_float4(0, 0, 0, 0);
    float4 nA = make_float4(0, 0, 0, 0), nB = make_float4(0, 0, 0, 0);

    // zero rings (avoid NaN from uninitialized smem)
    if (tid < 128) {
#pragma unroll
        for (int s = 0; s < 4; s++) { ksh[s][tid] = 0.f; vsh[s][tid] = 0.f; }
        qsh[0][tid] = 0.f; qsh[1][tid] = 0.f;
        ush[0][tid] = 0.f; ush[1][tid] = 0.f;
    }
    if (tid == 0) {
        coeff[0] = make_float4(1.f, 0.f, 0.f, 0.f);   // skip
        coeff[1] = make_float4(1.f, 0.f, 0.f, 0.f);
    }

    // staging source pointers (row 0), stage step 0 then advance to row 1
    const float* src = (seg == 0) ? q : (seg == 1) ? kg : (seg == 2) ? v : g_U;
    const float* sp = src + lane;
    {
        float x0 = sp[0];
        if (seg == 0)      qsh[0][lane] = x0;
        else if (seg == 1) ksh[0][lane] = x0;
        else if (seg == 2) vsh[0][lane] = x0;
        else               ush[0][lane] = x0;
        sp += DK;
    }
    if (tid < 32) {
        const float4* ch = (const float4*)g_chain;
        pA = ch[0]; pB = ch[1];
        nA = ch[2]; nB = ch[3];
    }
    __syncthreads();

    for (int i = 0; i <= SEQ; i++) {
        const int par = i & 1;

        // staging load for row i+1 (issued early; used next iteration)
        float nx = 0.f;
        if (i + 1 < SEQ) { nx = sp[0]; sp += DK; }

        // ---- deferred J update with coeffs of step i-2 ----------------------
        {
            float4 cc = coeff[par];
            if (!(cc.x == 1.f && cc.y == 0.f)) {
                const int s2i = (i - 2) & 3;
                const float bv = cc.y * vsh[s2i][row];
                const unsigned long long bvp = pk2(bv, bv);
                const ulonglong2* kp = (const ulonglong2*)&ksh[s2i][seg * 32];
                if (cc.x == 1.f) {
#pragma unroll
                    for (int c = 0; c < 8; c++) {
                        ulonglong2 kv = kp[c];
                        Jp[2 * c + 0] = ffma2(kv.x, bvp, Jp[2 * c + 0]);
                        Jp[2 * c + 1] = ffma2(kv.y, bvp, Jp[2 * c + 1]);
                    }
                } else {
                    const unsigned long long mp = pk2(cc.x, cc.x);
#pragma unroll
                    for (int c = 0; c < 8; c++) {
                        ulonglong2 kv = kp[c];
                        Jp[2 * c + 0] = ffma2(kv.x, bvp, fmul2(Jp[2 * c + 0], mp));
                        Jp[2 * c + 1] = ffma2(kv.y, bvp, fmul2(Jp[2 * c + 1], mp));
                    }
                }
            }
        }

        // ---- raw matvec partials vs Jhat: p1=(Jhat q_i)|, p2=(Jhat u_i)| ----
        if (i < SEQ) {
            unsigned long long a1a = 0ull, a1b = 0ull, a2a = 0ull, a2b = 0ull;
            const ulonglong2* qp = (const ulonglong2*)&qsh[par][seg * 32];
            const ulonglong2* up = (const ulonglong2*)&ush[par][seg * 32];
#pragma unroll
            for (int c2 = 0; c2 < 4; c2++) {
                ulonglong2 q0 = qp[2 * c2], q1 = qp[2 * c2 + 1];
                ulonglong2 u0 = up[2 * c2], u1 = up[2 * c2 + 1];
                a1a = ffma2(Jp[4 * c2 + 0], q0.x, a1a);
                a1b = ffma2(Jp[4 * c2 + 1], q0.y, a1b);
                a1a = ffma2(Jp[4 * c2 + 2], q1.x, a1a);
                a1b = ffma2(Jp[4 * c2 + 3], q1.y, a1b);
                a2a = ffma2(Jp[4 * c2 + 0], u0.x, a2a);
                a2b = ffma2(Jp[4 * c2 + 1], u0.y, a2b);
                a2a = ffma2(Jp[4 * c2 + 2], u1.x, a2a);
                a2b = ffma2(Jp[4 * c2 + 3], u1.y, a2b);
            }
            float2 f1a = upk2(a1a), f1b = upk2(a1b);
            float2 f2a = upk2(a2a), f2b = upk2(a2b);
            part[tid] = make_float2((f1a.x + f1a.y) + (f1b.x + f1b.y),
                                    (f2a.x + f2a.y) + (f2b.x + f2b.y));
        }

        // ---- stage row i+1 ---------------------------------------------------
        if (i + 1 < SEQ) {
            if (seg == 0)      qsh[1 - par][lane] = nx;
            else if (seg == 1) ksh[(i + 1) & 3][lane] = nx;
            else if (seg == 2) vsh[(i + 1) & 3][lane] = nx;
            else               ush[1 - par][lane] = nx;
        }

        // ---- split barrier: reduce warps wait, others pass through ----------
        if (tid >= 32 && tid < 160) {
            asm volatile("bar.sync 1, 512;" ::: "memory");
            if (i < SEQ) {
                const int j = tid - 32;
                float2 p0 = part[j], pa = part[j + 128];
                float2 pb = part[j + 256], pc = part[j + 384];
                float a = p0.x + pa.x + pb.x + pc.x;
                float b = p0.y + pa.y + pb.y + pc.y;
                float vl = vsh[i & 3][j];
                float vm = vsh[(i + 3) & 3][j];
                float x1 = vl * a, x2 = a * a, x3 = vl * b, x4 = vm * a;
#pragma unroll
                for (int o = 16; o > 0; o >>= 1) {
                    x1 += __shfl_down_sync(0xffffffffu, x1, o);
                    x2 += __shfl_down_sync(0xffffffffu, x2, o);
                    x3 += __shfl_down_sync(0xffffffffu, x3, o);
                    x4 += __shfl_down_sync(0xffffffffu, x4, o);
                }
                if ((tid & 31) == 0)
                    wsumb[par][(tid >> 5) - 1] = make_float4(x1, x2, x3, x4);
            }
        } else {
            asm volatile("bar.arrive 1, 512;" ::: "memory");
            // ---- warp 0: scalar chain for step l = i-1 ----------------------
            if (tid < 32 && i > 0) {
                const int l = i - 1;
                float4 w0 = wsumb[1 - par][0], w1 = wsumb[1 - par][1];
                float4 w2 = wsumb[1 - par][2], w3 = wsumb[1 - par][3];
                const float B1 = w0.x + w1.x + w2.x + w3.x;
                const float B2 = w0.y + w1.y + w2.y + w3.y;
                const float B3 = w0.z + w1.z + w2.z + w3.z;
                const float B4 = w0.w + w1.w + w2.w + w3.w;

                const float s_l = pA.x, kqq = pA.y, vvl = pA.z;
                const float kq = pB.x, ku = pB.y, vvm = pB.z;

                const float c2s = cp * sig_m;
                const float X1 = c2s * B1 + dp * kq * vvm;
                const float X3 = c2s * B3 + dp * ku * vvm;
                const float X2 = c2s * c2s * B2 + 2.f * c2s * dp * kq * B4
                               + dp * dp * kq * kq * vvprev;

                const float fl = (float)(l + 1);
                const float bmv = __fdividef(1.f, fl);
                const float amv = (fl - 1.f) * bmv;
                trS = amv * trS + vvl * bmv;
                const float sJ   = amv * S + bmv * X1;
                const float A_JJ = amv * T + bmv * X2;
                const float A_Jl = X3;
                const float A_ll = vvl * kqq;

                const bool first = (l == 0);
                const float A_JJ_s = (first || A_JJ == 0.f) ? 1.f : A_JJ;
                const float A_ll_s = (first || A_ll == 0.f) ? 1.f : A_ll;
                const float denom  = A_JJ * A_ll - A_Jl * A_Jl;
                const float denom_s = (first || denom == 0.f) ? 1.f : denom;

                const float margin = s_l - A_Jl * __fdividef(sJ, A_JJ_s);
                const float rden = __fdividef(1.f, denom_s);
                const float wf = (A_ll * sJ - A_Jl * s_l) * rden;
                const float wi = (A_JJ * s_l - A_Jl * sJ) * rden;
                const float wf_c = (wi <= 0.f) ? __fdividef(sJ, A_JJ_s)
                                               : ((wf <= 0.f) ? 0.f : wf);
                const float wi_c = (wi <= 0.f) ? 0.f
                                               : ((wf <= 0.f) ? __fdividef(s_l, A_ll_s) : wi);
                const bool do_upd = margin > 0.f;

                float cf, ci, upd;
                if (first)        { cf = 0.f; ci = 1.f;  upd = 1.f; S = s_l; T = A_ll; }
                else if (do_upd)  { cf = wf_c; ci = wi_c; upd = 1.f;
                                    S = cf * sJ + ci * s_l;
                                    T = cf * cf * A_JJ + 2.f * cf * ci * A_Jl + ci * ci * A_ll; }
                else              { cf = 1.f; ci = 0.f;  upd = 0.f; S = sJ; T = A_JJ; }

                if ((tid & 31) == 0) {
                    out[l] = 0.5f * trS - S + 0.5f * T;
                    out[SEQ + l] = upd;
                }

                float m, beta, signew;
                if (!(first || do_upd)) { m = 1.f; beta = 0.f; signew = sig_p; }
                else {
                    const float s2 = sig_p * cf;
                    if (cf == 0.f)                          { m = 0.f; beta = ci; signew = 1.f; }
                    else if (fabsf(s2) < 1e-12f || fabsf(s2) > 1e12f)
                                                            { m = s2;  beta = ci; signew = 1.f; }
                    else { m = 1.f; beta = __fdividef(ci, s2); signew = s2; }
                }
                if ((tid & 31) == 0) {
                    coeff[1 - par] = make_float4(m, beta, 0.f, 0.f);
                    if (i == SEQ) sigf = signew;
                }
                sig_m = sig_p; sig_p = signew;
                cp = cf; dp = ci; vvprev = vvl;
                pA = nA; pB = nB;
                if (l + 2 < SEQ) {
                    const float4* ch = (const float4*)g_chain;
                    nA = ch[2 * (l + 2)]; nB = ch[2 * (l + 2) + 1];
                }
            }
        }
        __syncthreads();
    }

    // ---- epilogue: apply final update (coeffs of step SEQ-1), scale out ----
    {
        float4 cc = coeff[1];
        if (!(cc.x == 1.f && cc.y == 0.f)) {
            const int s2i = (SEQ - 1) & 3;
            const float bv = cc.y * vsh[s2i][row];
            const unsigned long long bvp = pk2(bv, bv);
            const ulonglong2* kp = (const ulonglong2*)&ksh[s2i][seg * 32];
            if (cc.x == 1.f) {
#pragma unroll
                for (int c = 0; c < 8; c++) {
                    ulonglong2 kv = kp[c];
                    Jp[2 * c + 0] = ffma2(kv.x, bvp, Jp[2 * c + 0]);
                    Jp[2 * c + 1] = ffma2(kv.y, bvp, Jp[2 * c + 1]);
                }
            } else {
                const unsigned long long mp = pk2(cc.x, cc.x);
#pragma unroll
                for (int c = 0; c < 8; c++) {
                    ulonglong2 kv = kp[c];
                    Jp[2 * c + 0] = ffma2(kv.x, bvp, fmul2(Jp[2 * c + 0], mp));
                    Jp[2 * c + 1] = ffma2(kv.y, bvp, fmul2(Jp[2 * c + 1], mp));
                }
            }
        }
    }
    const float sf = sigf;
#pragma unroll
    for (int c = 0; c < 16; c++) {
        float2 jf = upk2(Jp[c]);
        out[2 * SEQ + (size_t)row * DK + seg * 32 + 2 * c + 0] = sf * jf.x;
        out[2 * SEQ + (size_t)row * DK + seg * 32 + 2 * c + 1] = sf * jf.y;
    }
}

// ---------------------------------------------------------------------------
extern "C" void kernel_launch(void* const* d_in, const int* in_sizes, int n_in,
                              void* d_out, int out_size) {
    const float* q = (const float*)d_in[0];
    const float* k = (const float*)d_in[1];
    const float* v = (const float*)d_in[2];
    float* out = (float*)d_out;

    dim3 gg(SEQ / 64, SEQ / 64, 2);
    k_gemm<<<gg, 256>>>(q, k, v);
    k_U<<<SEQ / 8, 256>>>(q);
    k_scal<<<SEQ / 64, 256>>>();
    k_adj<<<SEQ, 128>>>(q, k, v);
    k_seq<<<1, 512>>>(q, k, v, out);
    (void)in_sizes; (void)n_in; (void)out_size;
}